// round 8
// baseline (speedup 1.0000x reference)
#include <cuda_runtime.h>
#include <cuda_bf16.h>
#include <cstdint>

// ---------------- problem constants ----------------
#define V_REAL 50257
#define BN     128
#define NTILE  393                 // ceil(50257/128)
#define VPAD   (NTILE*BN)          // 50304
#define EDIM   512
#define MROWS  4096                // 4*1024
#define TOPK   8
#define NSEL   16                  // candidates rescored exactly

// GEMM tiling
#define BM 128
#define BK 32
#define NKC (EDIM/BK)              // 16
#define LDA 40                     // bf16 elems, padded (80B rows, 16B aligned)
#define LDB 40

#define FLT_MAX_ 3.402823466e+38f
#define TINY_F   1.17549435e-38f   // FLT_MIN (jnp.finfo(f32).tiny)
#define NORM_EPS 1e-12f

// Dynamic smem: A 2x(128*40*2)=20480, B 2x(128*40*2)=20480 -> 40960 (< 48KB)
#define SMEM_GEMM 40960

// ---------------- scratch (device globals; no allocation) ----------------
// Only referenced from device code (host-passing a __device__ symbol passes the
// host shadow address — the root bug of rounds 1-5).
static __device__ __nv_bfloat16 g_embn_bf16[(size_t)VPAD * EDIM];   // ~51.5 MB
static __device__ __nv_bfloat16 g_projn_bf16[(size_t)MROWS * EDIM]; // 4 MB
static __device__ float         g_scores[(size_t)MROWS * VPAD];     // ~824 MB

// ---------------- helpers ----------------
__device__ __forceinline__ void cp16(uint32_t dst, const void* src) {
    asm volatile("cp.async.cg.shared.global [%0], [%1], 16;\n" :: "r"(dst), "l"(src));
}
__device__ __forceinline__ void cp_commit() { asm volatile("cp.async.commit_group;\n" ::); }
__device__ __forceinline__ void cp_wait0()  { asm volatile("cp.async.wait_group 0;\n" ::); }

__device__ __forceinline__ void ldsm4(uint32_t* r, uint32_t addr) {
    asm volatile("ldmatrix.sync.aligned.m8n8.x4.shared.b16 {%0,%1,%2,%3}, [%4];\n"
                 : "=r"(r[0]), "=r"(r[1]), "=r"(r[2]), "=r"(r[3]) : "r"(addr));
}
__device__ __forceinline__ void mma16816(float* c, const uint32_t* a, const uint32_t* b) {
    asm volatile(
        "mma.sync.aligned.m16n8k16.row.col.f32.bf16.bf16.f32 "
        "{%0,%1,%2,%3}, {%4,%5,%6,%7}, {%8,%9}, {%0,%1,%2,%3};\n"
        : "+f"(c[0]), "+f"(c[1]), "+f"(c[2]), "+f"(c[3])
        : "r"(a[0]), "r"(a[1]), "r"(a[2]), "r"(a[3]), "r"(b[0]), "r"(b[1]));
}

__device__ __forceinline__ uint32_t rotl32(uint32_t v, int d) { return (v << d) | (v >> (32 - d)); }

// Exact JAX threefry2x32 block (key = [0, 42] for jax.random.key(42))
__device__ __forceinline__ uint2 threefry2x32(uint32_t k0, uint32_t k1, uint32_t x0, uint32_t x1) {
    uint32_t ks2 = k0 ^ k1 ^ 0x1BD11BDAu;
    x0 += k0; x1 += k1;
#define TF_R4(a,b,c,d) \
    { x0 += x1; x1 = rotl32(x1,a); x1 ^= x0; \
      x0 += x1; x1 = rotl32(x1,b); x1 ^= x0; \
      x0 += x1; x1 = rotl32(x1,c); x1 ^= x0; \
      x0 += x1; x1 = rotl32(x1,d); x1 ^= x0; }
    TF_R4(13,15,26,6);  x0 += k1;  x1 += ks2 + 1u;
    TF_R4(17,29,16,24); x0 += ks2; x1 += k0  + 2u;
    TF_R4(13,15,26,6);  x0 += k0;  x1 += k1  + 3u;
    TF_R4(17,29,16,24); x0 += k1;  x1 += ks2 + 4u;
    TF_R4(13,15,26,6);  x0 += ks2; x1 += k0  + 5u;
#undef TF_R4
    return make_uint2(x0, x1);
}

// JAX partitionable threefry random_bits, bit_width=32:
//   counts1, counts2 = iota_2x32_shape(shape)   (hi, lo words of flat index)
//   bits1, bits2 = threefry2x32(key, counts1, counts2)
//   return bits1 ^ bits2        <-- XOR fold for 8/16/32-bit widths
__device__ __forceinline__ uint32_t jax_random_bits32(uint32_t i) {
    uint2 o = threefry2x32(0u, 42u, 0u, i);   // hi(i)=0 for i < 2^32
    return o.x ^ o.y;
}

// ---------------- kernel 1/2: row L2 normalize -> bf16 (dst chosen in DEVICE code) ----------------
__global__ void normalize_kernel(const float* __restrict__ src,
                                 int real_rows, int which) {
    __nv_bfloat16* dstb = which ? g_projn_bf16 : g_embn_bf16;   // device-side symbol ref
    int r = blockIdx.x;          // one row per CTA, 128 threads
    int tid = threadIdx.x;
    if (r >= real_rows) {        // zero-pad rows (embeddings padding)
        ushort4 z; z.x = z.y = z.z = z.w = 0;
        ((ushort4*)(dstb + (size_t)r * EDIM))[tid] = z;
        return;
    }
    float4 v = ((const float4*)(src + (size_t)r * EDIM))[tid];
    float ss = v.x * v.x + v.y * v.y + v.z * v.z + v.w * v.w;
    #pragma unroll
    for (int o = 16; o; o >>= 1) ss += __shfl_xor_sync(0xffffffffu, ss, o);
    __shared__ float wsum[4];
    if ((tid & 31) == 0) wsum[tid >> 5] = ss;
    __syncthreads();
    float tot = wsum[0] + wsum[1] + wsum[2] + wsum[3];
    float denom = fmaxf(sqrtf(tot), NORM_EPS);
    ushort4 b;
    b.x = __bfloat16_as_ushort(__float2bfloat16(v.x / denom));
    b.y = __bfloat16_as_ushort(__float2bfloat16(v.y / denom));
    b.z = __bfloat16_as_ushort(__float2bfloat16(v.z / denom));
    b.w = __bfloat16_as_ushort(__float2bfloat16(v.w / denom));
    ((ushort4*)(dstb + (size_t)r * EDIM))[tid] = b;
}

// ---------------- kernel 3: bf16 MMA GEMM (128x128 tile) -> full fp32 scores ----------------
// grid (NTILE, MROWS/BM), block 256 (8 warps: 4 over M x 2 over N, warp tile 32x64)
__global__ void __launch_bounds__(256) gemm_kernel() {
    extern __shared__ char smem[];
    const int tid = threadIdx.x, lane = tid & 31, wid = tid >> 5;
    const int bn = blockIdx.x, bm = blockIdx.y;
    const int m0 = bm * BM, n0 = bn * BN;

    uint32_t sbase = (uint32_t)__cvta_generic_to_shared(smem);
    uint32_t aBase[2] = { sbase,                    sbase + BM * LDA * 2 };
    uint32_t bBase[2] = { sbase + 2 * BM * LDA * 2, sbase + 2 * BM * LDA * 2 + BN * LDB * 2 };

    float acc[2][8][4];
    #pragma unroll
    for (int mi = 0; mi < 2; mi++)
        #pragma unroll
        for (int ni = 0; ni < 8; ni++)
            #pragma unroll
            for (int q = 0; q < 4; q++) acc[mi][ni][q] = 0.f;

    const int wm0 = (wid >> 1) * 32;     // 4 warps over M
    const int wn0 = (wid & 1) * 64;      // 2 warps over N

    auto loadA = [&](int kc, int buf) {
        const __nv_bfloat16* gp = g_projn_bf16 + (size_t)m0 * EDIM + kc * BK;
        #pragma unroll
        for (int i = 0; i < 2; i++) {
            int vId = tid + i * 256;
            int row = vId >> 2, q = vId & 3;
            cp16(aBase[buf] + (row * LDA + q * 8) * 2, gp + (size_t)row * EDIM + q * 8);
        }
    };
    auto loadB = [&](int kc, int buf) {
        const __nv_bfloat16* gb = g_embn_bf16 + (size_t)n0 * EDIM + kc * BK;
        #pragma unroll
        for (int i = 0; i < 2; i++) {
            int vId = tid + i * 256;
            int row = vId >> 2, q = vId & 3;
            cp16(bBase[buf] + (row * LDB + q * 8) * 2, gb + (size_t)row * EDIM + q * 8);
        }
    };

    loadA(0, 0); loadB(0, 0); cp_commit();

    const int aRow = lane & 15;                    // ldmatrix A addressing
    const int aK   = (lane >> 4) << 3;
    const int bN   = (lane & 7) + (((lane >> 4) & 1) << 3);
    const int bK   = ((lane >> 3) & 1) << 3;

    for (int kc = 0; kc < NKC; kc++) {
        cp_wait0();
        __syncthreads();
        if (kc + 1 < NKC) { loadA(kc + 1, (kc + 1) & 1); loadB(kc + 1, (kc + 1) & 1); cp_commit(); }
        int buf = kc & 1;
        #pragma unroll
        for (int s = 0; s < 2; s++) {
            uint32_t a[2][4], b[8][2];
            int k16 = s * 16;
            #pragma unroll
            for (int mi = 0; mi < 2; mi++) {
                uint32_t addr = aBase[buf] + (((wm0 + mi * 16 + aRow) * LDA) + k16 + aK) * 2;
                ldsm4(a[mi], addr);
            }
            #pragma unroll
            for (int p = 0; p < 4; p++) {
                uint32_t tmp[4];
                uint32_t addr = bBase[buf] + (((wn0 + p * 16 + bN) * LDB) + k16 + bK) * 2;
                ldsm4(tmp, addr);
                b[2 * p][0] = tmp[0]; b[2 * p][1] = tmp[1];
                b[2 * p + 1][0] = tmp[2]; b[2 * p + 1][1] = tmp[3];
            }
            #pragma unroll
            for (int mi = 0; mi < 2; mi++)
                #pragma unroll
                for (int ni = 0; ni < 8; ni++)
                    mma16816(acc[mi][ni], a[mi], b[ni]);
        }
    }

    // ---- epilogue: textbook fragment -> global fp32 scores ----
    const int g = lane >> 2, t4 = lane & 3;
    #pragma unroll
    for (int mi = 0; mi < 2; mi++)
        #pragma unroll
        for (int ni = 0; ni < 8; ni++) {
            int r = m0 + wm0 + mi * 16 + g;
            int c = n0 + wn0 + ni * 8 + t4 * 2;
            *(float2*)&g_scores[(size_t)r * VPAD + c] =
                make_float2(acc[mi][ni][0], acc[mi][ni][1]);
            *(float2*)&g_scores[(size_t)(r + 8) * VPAD + c] =
                make_float2(acc[mi][ni][2], acc[mi][ni][3]);
        }
}

// ---------------- kernel 4: per-row top-k from full scores, rescore, sample ----------------
__global__ void __launch_bounds__(256) topk_sample_kernel(const float* __restrict__ proj_raw,
                                                          const float* __restrict__ emb_raw,
                                                          float* __restrict__ out) {
    __shared__ float sh_proj[EDIM];
    __shared__ float sv[256 * TOPK];
    __shared__ int   si[256 * TOPK];
    __shared__ float red_v[8];
    __shared__ int   red_p[8];
    __shared__ int   sidx[NSEL];
    __shared__ float strue[NSEL];
    __shared__ float pnorm2[8];

    const int row = blockIdx.x;
    const int tid = threadIdx.x, lane = tid & 31, wid = tid >> 5;

    // normalize raw projection row into sh_proj
    {
        float ss = 0.f;
        for (int j = tid; j < EDIM; j += 256) {
            float x = proj_raw[(size_t)row * EDIM + j];
            sh_proj[j] = x;
            ss += x * x;
        }
        #pragma unroll
        for (int o = 16; o; o >>= 1) ss += __shfl_xor_sync(0xffffffffu, ss, o);
        if (lane == 0) pnorm2[wid] = ss;
        __syncthreads();
        float tot = 0.f;
        #pragma unroll
        for (int w = 0; w < 8; w++) tot += pnorm2[w];
        float denom = fmaxf(sqrtf(tot), NORM_EPS);
        __syncthreads();
        for (int j = tid; j < EDIM; j += 256) sh_proj[j] = sh_proj[j] / denom;
    }

    // thread-local top-8 scan over this row's scores (coalesced stride-256)
    float tv[TOPK]; int ti[TOPK];
    #pragma unroll
    for (int k = 0; k < TOPK; k++) { tv[k] = -FLT_MAX_; ti[k] = -1; }
    const float* srow = g_scores + (size_t)row * VPAD;
    for (int j = tid; j < V_REAL; j += 256) {
        float v = srow[j];
        if (v <= tv[TOPK - 1]) continue;
        int p = TOPK - 1;
        while (p > 0 && tv[p - 1] < v) { tv[p] = tv[p - 1]; ti[p] = ti[p - 1]; p--; }
        tv[p] = v; ti[p] = j;
    }
    #pragma unroll
    for (int k = 0; k < TOPK; k++) { sv[tid * TOPK + k] = tv[k]; si[tid * TOPK + k] = ti[k]; }
    __syncthreads();

    // block top-NSEL via iterative argmax over the 2048 staged candidates
    for (int it = 0; it < NSEL; it++) {
        float bv = -FLT_MAX_; int bp = 0;
        #pragma unroll
        for (int k = 0; k < TOPK; k++) {
            int j = tid + k * 256;
            float v = sv[j];
            if (v > bv) { bv = v; bp = j; }
        }
        #pragma unroll
        for (int o = 16; o; o >>= 1) {
            float ov = __shfl_down_sync(0xffffffffu, bv, o);
            int   op = __shfl_down_sync(0xffffffffu, bp, o);
            if (ov > bv) { bv = ov; bp = op; }
        }
        if (lane == 0) { red_v[wid] = bv; red_p[wid] = bp; }
        __syncthreads();
        if (tid == 0) {
            float m = red_v[0]; int p = red_p[0];
            #pragma unroll
            for (int w = 1; w < 8; w++) if (red_v[w] > m) { m = red_v[w]; p = red_p[w]; }
            sidx[it] = si[p];
            sv[p] = -FLT_MAX_;
        }
        __syncthreads();
    }

    // exact fp32 rescore: s = <proj_n, emb_raw[idx]> / max(||emb_raw[idx]||, eps)
    for (int c = wid; c < NSEL; c += 8) {
        int idx = sidx[c];
        float s = 0.f, e2 = 0.f;
        if (idx >= 0) {
            const float* e = emb_raw + (size_t)idx * EDIM;
            for (int j = lane; j < EDIM; j += 32) {
                float ev = e[j];
                s  = fmaf(sh_proj[j], ev, s);
                e2 = fmaf(ev, ev, e2);
            }
        }
        #pragma unroll
        for (int o = 16; o; o >>= 1) {
            s  += __shfl_xor_sync(0xffffffffu, s, o);
            e2 += __shfl_xor_sync(0xffffffffu, e2, o);
        }
        if (lane == 0) strue[c] = (idx >= 0) ? s / fmaxf(sqrtf(e2), NORM_EPS) : -FLT_MAX_;
    }
    __syncthreads();

    if (tid == 0) {
        // stable top-8: val desc, index asc (matches lax.top_k)
        float fv[TOPK]; int fi[TOPK];
        unsigned used = 0;
        for (int r = 0; r < TOPK; r++) {
            int best = -1; float bv = 0.f; int bi = 0;
            for (int c = 0; c < NSEL; c++) {
                if ((used >> c) & 1u) continue;
                float v = strue[c]; int ix = sidx[c];
                if (best < 0 || v > bv || (v == bv && ix < bi)) { best = c; bv = v; bi = ix; }
            }
            used |= 1u << best;
            fv[r] = bv; fi[r] = bi;
        }
        // gumbel-argmax sampling — partitionable threefry (xor-fold) scheme
        float m = -FLT_MAX_; int arg = 0;
        #pragma unroll
        for (int k = 0; k < TOPK; k++) {
            unsigned i = (unsigned)row * TOPK + k;
            unsigned bits = jax_random_bits32(i);
            float f = __uint_as_float((bits >> 9) | 0x3f800000u) - 1.0f;
            float u = fmaxf(TINY_F, f);
            float gmb = -logf(-logf(u));
            float t = fv[k] + gmb;     // TEMPERATURE = 1.0
            if (t > m) { m = t; arg = k; }
        }
        out[row] = (float)fi[arg];     // output compared as float32
    }
}

// ---------------- launcher ----------------
extern "C" void kernel_launch(void* const* d_in, const int* in_sizes, int n_in,
                              void* d_out, int out_size) {
    // Robust input resolution: largest input = embeddings, 2nd largest = projections.
    int ie = 0, ip = 0;
    long b1 = -1, b2 = -1;
    for (int i = 0; i < n_in; i++) {
        long s = in_sizes[i];
        if (s > b1)      { b2 = b1; ip = ie; b1 = s; ie = i; }
        else if (s > b2) { b2 = s; ip = i; }
    }
    const float* emb  = (const float*)d_in[ie];   // [50257,512]
    const float* proj = (const float*)d_in[ip];   // [4,1024,512]
    float* out = (float*)d_out;                   // [4,1024] float32 token ids

    normalize_kernel<<<VPAD, 128>>>(emb, V_REAL, /*which=*/0);
    normalize_kernel<<<MROWS, 128>>>(proj, MROWS, /*which=*/1);
    gemm_kernel<<<dim3(NTILE, MROWS / BM), 256, SMEM_GEMM>>>();
    topk_sample_kernel<<<MROWS, 256>>>(proj, emb, out);
}